// round 15
// baseline (speedup 1.0000x reference)
#include <cuda_runtime.h>
#include <cuda_fp16.h>
#include <cstdint>

#define N_DIM 16384
#define D_DIM 10240
#define C_DIM 128
#define NUM_CHUNK 160              // chunks of 64 k
#define THREADS 256
#define LSTRIDE 144                // bytes per (kstep,lane) slot row: 16 n*8B + 16 pad
#define STAGE_BYTES (4 * 32 * LSTRIDE)       // 18432
#define STAGE_UNITS (STAGE_BYTES / 16)       // 1152
#define STAGES 4
#define SMEM_BYTES (STAGES * STAGE_BYTES)    // 73728

// am pre-packed to the FINAL smem image: for chunk ch, kstep j, lane l
// (lg=l>>2, lt=l&3), slot n (0..15) at byte ch*18432 + (j*32+l)*144 + n*8
// holds f16x2{k,k+1}, f16x2{k+8,k+9} of class c = n*8+lg, k = ch*64+j*16+lt*2.
__device__ __align__(16) uint2 g_bm[(size_t)NUM_CHUNK * STAGE_BYTES / 8];

static __device__ __forceinline__ bool is_am8(const float* a) {
    bool r = true;
#pragma unroll
    for (int i = 0; i < 8; ++i) {
        float v = __ldg(a + i);
        r &= (v == 1.0f || v == -1.0f);
    }
    return r;
}

static __device__ __forceinline__ uint32_t smem_u32(const void* p) {
    uint32_t a;
    asm("{ .reg .u64 t; cvta.to.shared.u64 t, %1; cvt.u32.u64 %0, t; }" : "=r"(a) : "l"(p));
    return a;
}
static __device__ __forceinline__ uint32_t f16x2_rn(float2 v) {
    __half2 h2 = __float22half2_rn(v);
    return reinterpret_cast<uint32_t&>(h2);
}
// 2-way exact split of a float2 into f16x2 hi/mid
static __device__ __forceinline__ void split2(float2 v, uint32_t& h, uint32_t& m) {
    __half2 h2 = __float22half2_rn(v);
    float2 hf = __half22float2(h2);
    __half2 m2 = __float22half2_rn(make_float2(v.x - hf.x, v.y - hf.y));
    h = reinterpret_cast<uint32_t&>(h2);
    m = reinterpret_cast<uint32_t&>(m2);
}

// Pack kernel: one thread per 8-byte slot; 160*4*32*16 = 327680 threads.
__global__ void am_pack_kernel(const float* a, const float* b) {
    const float* am = is_am8(a) ? a : b;
    int idx = blockIdx.x * blockDim.x + threadIdx.x;
    int n  = idx & 15;
    int l  = (idx >> 4) & 31;
    int j  = (idx >> 9) & 3;
    int ch = idx >> 11;
    int c  = n * 8 + (l >> 2);
    int k  = ch * 64 + j * 16 + (l & 3) * 2;
    const float* p = am + (size_t)c * D_DIM + k;
    g_bm[(size_t)ch * 2304 + (j * 32 + l) * 18 + n] =
        make_uint2(f16x2_rn(*(const float2*)p), f16x2_rn(*(const float2*)(p + 8)));
}

// fp32-accum MMA (hi split)
#define MMA_F32(d, a0_, a1_, a2_, a3_, b0_, b1_)                                  \
    asm volatile("mma.sync.aligned.m16n8k16.row.col.f32.f16.f16.f32 "             \
                 "{%0,%1,%2,%3}, {%4,%5,%6,%7}, {%8,%9}, {%0,%1,%2,%3};"          \
                 : "+f"((d)[0]), "+f"((d)[1]), "+f"((d)[2]), "+f"((d)[3])         \
                 : "r"(a0_), "r"(a1_), "r"(a2_), "r"(a3_), "r"(b0_), "r"(b1_))

// fp16-accum MMA (mid split; values ~1e-1, rounding ~1e-3 total)
#define MMA_F16(d, a0_, a1_, a2_, a3_, b0_, b1_)                                  \
    asm volatile("mma.sync.aligned.m16n8k16.row.col.f16.f16.f16.f16 "             \
                 "{%0,%1}, {%2,%3,%4,%5}, {%6,%7}, {%0,%1};"                      \
                 : "+r"((d)[0]), "+r"((d)[1])                                     \
                 : "r"(a0_), "r"(a1_), "r"(a2_), "r"(a3_), "r"(b0_), "r"(b1_))

__global__ void __launch_bounds__(THREADS, 1)
hd_mma_kernel(const float* __restrict__ a, const float* __restrict__ b,
              float* __restrict__ out) {
    extern __shared__ __align__(16) char smb[];
    const uint32_t sb = smem_u32(smb);

    const float* __restrict__ x = is_am8(a) ? b : a;

    const int tid = threadIdx.x;
    const int w = tid >> 5, l = tid & 31;
    const int lg = l >> 2;        // lane group = row within m16 tile (PTX A frag)
    const int lt = l & 3;         // thread in group (PTX A frag)

    // ---- A: direct-gmem fragment pointers (PTX m16n8k16 A layout) ----
    const float* pr0 = x + ((size_t)blockIdx.x * 128 + w * 16 + lg) * D_DIM + lt * 2;
    const float* pr8 = pr0 + (size_t)8 * D_DIM;

    float acc[16][4];
    uint32_t accm[16][2];
#pragma unroll
    for (int n = 0; n < 16; ++n) {
#pragma unroll
        for (int e = 0; e < 4; ++e) acc[n][e] = 0.0f;
        accm[n][0] = 0u; accm[n][1] = 0u;
    }

    // cp.async: linear stage copy, 1152 16-B units over 256 threads
    auto issue_b = [&](int ci) {
        uint32_t dst = sb + (uint32_t)(ci & (STAGES - 1)) * STAGE_BYTES;
        const char* src = (const char*)g_bm + (size_t)ci * STAGE_BYTES;
#pragma unroll
        for (int i = 0; i < 5; ++i) {
            int u = tid + i * 256;
            if (u < STAGE_UNITS)
                asm volatile("cp.async.cg.shared.global [%0], [%1], 16;"
                             :: "r"(dst + (uint32_t)(u * 16)),
                                "l"(src + (size_t)u * 16) : "memory");
        }
        asm volatile("cp.async.commit_group;" ::: "memory");
    };

    issue_b(0); issue_b(1); issue_b(2);

    // A register prefetch: full chunk (4 ksteps x 4 fragments), refilled in place.
    float2 va[4][4];
#pragma unroll
    for (int j = 0; j < 4; ++j) {
        const int off = j * 16;
        va[j][0] = *(const float2*)(pr0 + off);
        va[j][1] = *(const float2*)(pr8 + off);
        va[j][2] = *(const float2*)(pr0 + off + 8);
        va[j][3] = *(const float2*)(pr8 + off + 8);
    }

    // Current splits (kstep 0), pipelined one kstep ahead thereafter.
    uint32_t ahc[4], amc[4];
#pragma unroll
    for (int q = 0; q < 4; ++q) split2(va[0][q], ahc[q], amc[q]);

    const uint32_t lbase = (uint32_t)(l * LSTRIDE);

    for (int ch = 0; ch < NUM_CHUNK; ++ch) {
        asm volatile("cp.async.wait_group 2;" ::: "memory");
        __syncthreads();
        if (ch + 3 < NUM_CHUNK) issue_b(ch + 3);
        else asm volatile("cp.async.commit_group;" ::: "memory");  // keep cadence

        const bool more = (ch + 1 < NUM_CHUNK);
        const uint32_t stage = sb + (uint32_t)(ch & (STAGES - 1)) * STAGE_BYTES + lbase;

#pragma unroll
        for (int j = 0; j < 4; ++j) {
            // B loads: 8x LDS.128, conflict-free (36-word lane stride)
            uint32_t breg[32];
            const uint32_t bbase = stage + (uint32_t)(j * 32 * LSTRIDE);
#pragma unroll
            for (int i = 0; i < 8; ++i)
                asm volatile("ld.shared.v4.b32 {%0, %1, %2, %3}, [%4];"
                             : "=r"(breg[4 * i]), "=r"(breg[4 * i + 1]),
                               "=r"(breg[4 * i + 2]), "=r"(breg[4 * i + 3])
                             : "r"(bbase + (uint32_t)(i * 16)));

            // Pipeline: split NEXT kstep's A now (va[(j+1)&3]; at j==3 this is
            // next chunk's kstep 0, refilled at j==0)
            uint32_t ahn[4], amn[4];
#pragma unroll
            for (int q = 0; q < 4; ++q) split2(va[(j + 1) & 3][q], ahn[q], amn[q]);

            // Refill va[j] from next chunk (load->use distance = 4 ksteps)
            if (more) {
                const int off = (ch + 1) * 64 + j * 16;
                va[j][0] = *(const float2*)(pr0 + off);
                va[j][1] = *(const float2*)(pr8 + off);
                va[j][2] = *(const float2*)(pr0 + off + 8);
                va[j][3] = *(const float2*)(pr8 + off + 8);
            }

            // Interleaved MMA streams: alternating fp32/fp16 accumulators
#pragma unroll
            for (int n = 0; n < 16; ++n) {
                MMA_F32(acc[n], ahc[0], ahc[1], ahc[2], ahc[3],
                        breg[2 * n], breg[2 * n + 1]);
                MMA_F16(accm[n], amc[0], amc[1], amc[2], amc[3],
                        breg[2 * n], breg[2 * n + 1]);
            }

            // rotate splits
#pragma unroll
            for (int q = 0; q < 4; ++q) { ahc[q] = ahn[q]; amc[q] = amn[q]; }
        }
    }

    // ---- epilogue: merge hi + mid, per-row first-max argmax ----
#pragma unroll
    for (int h = 0; h < 2; ++h) {
        float best = -3.402823466e38f;
        int bi = 0;
#pragma unroll
        for (int n = 0; n < 16; ++n) {
            __half2 mh = reinterpret_cast<__half2&>(accm[n][h]);
            float2 mf = __half22float2(mh);
            float v0 = acc[n][h * 2] + mf.x;
            float v1 = acc[n][h * 2 + 1] + mf.y;
            int c = n * 8 + lt * 2;
            if (v0 > best) { best = v0; bi = c; }
            if (v1 > best) { best = v1; bi = c + 1; }
        }
#pragma unroll
        for (int ofs = 1; ofs < 4; ofs <<= 1) {
            float ov = __shfl_xor_sync(0xffffffffu, best, ofs);
            int oi = __shfl_xor_sync(0xffffffffu, bi, ofs);
            if (ov > best || (ov == best && oi < bi)) { best = ov; bi = oi; }
        }
        if (lt == 0)
            out[blockIdx.x * 128 + w * 16 + h * 8 + lg] = (float)bi;  // float32 output
    }
}

extern "C" void kernel_launch(void* const* d_in, const int* in_sizes, int n_in,
                              void* d_out, int out_size) {
    const float* a = (const float*)d_in[0];
    const float* b = (const float*)d_in[1];

    am_pack_kernel<<<(NUM_CHUNK * 4 * 32 * 16) / 256, 256>>>(a, b);

    cudaFuncSetAttribute(hd_mma_kernel,
                         cudaFuncAttributeMaxDynamicSharedMemorySize, SMEM_BYTES);
    hd_mma_kernel<<<N_DIM / 128, THREADS, SMEM_BYTES>>>(a, b, (float*)d_out);
}